// round 8
// baseline (speedup 1.0000x reference)
#include <cuda_runtime.h>
#include <cuda_bf16.h>
#include <cstdint>

#define NQ 2048
#define NB 8192
#define DIM 32
#define TPB 512
#define QPC 256            // queries per CTA
#define BSPL 18            // background splits (grid.y), uneven on group granularity
#define GW  32             // group width in b
#define GTOT (NB / GW)     // 256 total groups
#define MAXG 15            // max groups per CTA
#define MAXB (MAXG * GW)   // 480 rows
#define STRIDE 144         // SMEM row stride bytes (odd*16 -> ldsm conflict-free)
#define DSTR 40            // dot buffer stride floats (conflict-free STS.64)
#define LOG2E 1.4426950408889634f

// ---------------- device scratch ----------------
__device__ float g_pk [NQ * BSPL];
__device__ float g_pky[NQ * BSPL];
__device__ int   g_cnt[NQ / QPC];      // arrival counters (zero-init, self-resetting)

// ---------------- helpers ----------------
__device__ __forceinline__ uint32_t smem_u32(const void* p) {
    uint32_t a;
    asm("{ .reg .u64 t; cvta.to.shared.u64 t, %1; cvt.u32.u64 %0, t; }" : "=r"(a) : "l"(p));
    return a;
}
__device__ __forceinline__ void ldsm_x4(uint32_t* r, uint32_t addr) {
    asm volatile("ldmatrix.sync.aligned.m8n8.x4.shared.b16 {%0,%1,%2,%3}, [%4];"
                 : "=r"(r[0]), "=r"(r[1]), "=r"(r[2]), "=r"(r[3]) : "r"(addr));
}
__device__ __forceinline__ void mma_bf16(float* d, const uint32_t* a, const uint32_t* b) {
    asm volatile(
        "mma.sync.aligned.m16n8k16.row.col.f32.bf16.bf16.f32 "
        "{%0,%1,%2,%3}, {%4,%5,%6,%7}, {%8,%9}, {%0,%1,%2,%3};"
        : "+f"(d[0]), "+f"(d[1]), "+f"(d[2]), "+f"(d[3])
        : "r"(a[0]), "r"(a[1]), "r"(a[2]), "r"(a[3]), "r"(b[0]), "r"(b[1]));
}
__device__ __forceinline__ float ex2a(float x) {
    float y; asm("ex2.approx.ftz.f32 %0, %1;" : "=f"(y) : "f"(x)); return y;
}
__device__ __forceinline__ float sqrta(float x) {
    float y; asm("sqrt.approx.f32 %0, %1;" : "=f"(y) : "f"(x)); return y;
}

// transpose-reduce 16 regs over 32 lanes; lane L ends holding total for idx (L>>1)&15
__device__ __forceinline__ float treduce16(float* v, int lane) {
#pragma unroll
    for (int o = 16; o >= 2; o >>= 1) {
        bool up = (lane & o) != 0;
#pragma unroll
        for (int j = 0; j < 16; ++j) {
            if (j < (o >> 1)) {
                float send = up ? v[j] : v[j + (o >> 1)];
                float recv = __shfl_xor_sync(0xffffffffu, send, o);
                float keep = up ? v[j + (o >> 1)] : v[j];
                v[j] = keep + recv;
            }
        }
    }
    return v[0] + __shfl_xor_sync(0xffffffffu, v[0], 1);
}

// ---------------- SMEM layout ----------------
#define SM_A   0                               // 256*144 = 36864
#define SM_B   36864                           // 480*144 = 69120
#define SM_DOT 105984                          // 16 warps * 2 bufs * 2560 = 81920
#define DBUF   (16 * DSTR * 4)                 // 2560 bytes per buffer
#define SM_B2  187904                          // 1920
#define SM_YB  189824                          // 1920
#define SM_Q2  191744                          // 1024
#define SMEM_TOTAL 192768

// convert 8 floats to hi/lo bf16 packs (4 uint32 each)
__device__ __forceinline__ void cvt8(const float* v, uint32_t* hi, uint32_t* lo) {
#pragma unroll
    for (int j = 0; j < 4; ++j) {
        float2 p = make_float2(v[2 * j], v[2 * j + 1]);
        __nv_bfloat162 h = __float22bfloat162_rn(p);
        hi[j] = *(uint32_t*)&h;
        float2 rres = make_float2(p.x - __bfloat162float(h.x),
                                  p.y - __bfloat162float(h.y));
        __nv_bfloat162 l = __float22bfloat162_rn(rres);
        lo[j] = *(uint32_t*)&l;
    }
}

// ---- MMA + STS stage for one group (writes dbuf) ----
__device__ __forceinline__ void mma_sts(int s, float* dbuf,
                                        uint32_t bA, uint32_t bB,
                                        const uint32_t afr[4][4],
                                        float q2a, float q2b, int lane) {
    uint32_t bf01[4][4], bf23[4][4];
#pragma unroll
    for (int c = 0; c < 4; ++c) {
        ldsm_x4(bf01[c], bA + s * (GW * STRIDE) + c * 32);
        ldsm_x4(bf23[c], bB + s * (GW * STRIDE) + c * 32);
    }
    float acc[4][4];
#pragma unroll
    for (int nt = 0; nt < 4; ++nt)
#pragma unroll
        for (int k = 0; k < 4; ++k) acc[nt][k] = 0.f;
    const int pa[6] = {0, 1, 2, 3, 0, 1};
    const int pb[6] = {0, 1, 0, 1, 2, 3};
#pragma unroll
    for (int p = 0; p < 6; ++p) {
        mma_bf16(acc[0], afr[pa[p]], bf01[pb[p]] + 0);
        mma_bf16(acc[1], afr[pa[p]], bf01[pb[p]] + 2);
        mma_bf16(acc[2], afr[pa[p]], bf23[pb[p]] + 0);
        mma_bf16(acc[3], afr[pa[p]], bf23[pb[p]] + 2);
    }
    int row = (lane >> 2), col = (lane & 3) * 2;
#pragma unroll
    for (int nt = 0; nt < 4; ++nt) {
        *(float2*)(dbuf + row * DSTR + nt * 8 + col) =
            make_float2(fmaf(-2.f, acc[nt][0], q2a), fmaf(-2.f, acc[nt][1], q2a));
        *(float2*)(dbuf + (row + 8) * DSTR + nt * 8 + col) =
            make_float2(fmaf(-2.f, acc[nt][2], q2b), fmaf(-2.f, acc[nt][3], q2b));
    }
}

// ---------------- fused kernel ----------------
__global__ void __launch_bounds__(TPB, 1)
main_kernel(const float* __restrict__ xb_g, const float* __restrict__ yb,
            const float* __restrict__ xq_g, const float* __restrict__ r,
            const float* __restrict__ sigma, const float* __restrict__ rscale,
            const float* __restrict__ w, float* __restrict__ out) {
    extern __shared__ char smem[];
    __shared__ int is_last;
    const uint32_t sbase = smem_u32(smem);
    const int tid = threadIdx.x, wid = tid >> 5, lane = tid & 31;
    const int q0 = blockIdx.x * QPC;
    const int g0 = (blockIdx.y * GTOT) / BSPL;
    const int g1 = ((blockIdx.y + 1) * GTOT) / BSPL;
    const int ngrp = g1 - g0;                  // 14 or 15
    const int b0 = g0 * GW;
    const int nrows = ngrp * GW;
    const int qw = wid * 16;
    const int part = tid & 3;

    const float c1 = -LOG2E / __ldg(sigma);
    const float c2 = __ldg(rscale) * LOG2E;

    // ---- in-CTA prep: scale by w, split bf16 [hi|lo] ----
    float wreg[8];
    *(float4*)(wreg)     = __ldg((const float4*)(w + part * 8));
    *(float4*)(wreg + 4) = __ldg((const float4*)(w + part * 8 + 4));

    float* q2s = (float*)(smem + SM_Q2);
    float* b2s = (float*)(smem + SM_B2);

#pragma unroll
    for (int i = 0; i < 2; ++i) {              // A (queries): 256 rows
        int ch = tid + i * TPB, row = ch >> 2;
        float v[8];
        *(float4*)(v)     = __ldg((const float4*)(xq_g + (size_t)(q0 + row) * DIM + part * 8));
        *(float4*)(v + 4) = __ldg((const float4*)(xq_g + (size_t)(q0 + row) * DIM + part * 8 + 4));
        float s = 0.f;
#pragma unroll
        for (int j = 0; j < 8; ++j) { v[j] *= wreg[j]; s = fmaf(v[j], v[j], s); }
        uint32_t hi[4], lo[4];
        cvt8(v, hi, lo);
        char* base = smem + SM_A + row * STRIDE + part * 16;
        *(uint4*)(base)      = make_uint4(hi[0], hi[1], hi[2], hi[3]);
        *(uint4*)(base + 64) = make_uint4(lo[0], lo[1], lo[2], lo[3]);
        s += __shfl_xor_sync(0xffffffffu, s, 1);
        s += __shfl_xor_sync(0xffffffffu, s, 2);
        if (part == 0) q2s[row] = s;
    }
#pragma unroll
    for (int i = 0; i < 4; ++i) {              // B (backgrounds): nrows <= 480
        int ch = tid + i * TPB;
        if (ch < nrows * 4) {
            int row = ch >> 2;
            float v[8];
            *(float4*)(v)     = __ldg((const float4*)(xb_g + (size_t)(b0 + row) * DIM + part * 8));
            *(float4*)(v + 4) = __ldg((const float4*)(xb_g + (size_t)(b0 + row) * DIM + part * 8 + 4));
            float s = 0.f;
#pragma unroll
            for (int j = 0; j < 8; ++j) { v[j] *= wreg[j]; s = fmaf(v[j], v[j], s); }
            uint32_t hi[4], lo[4];
            cvt8(v, hi, lo);
            char* base = smem + SM_B + row * STRIDE + part * 16;
            *(uint4*)(base)      = make_uint4(hi[0], hi[1], hi[2], hi[3]);
            *(uint4*)(base + 64) = make_uint4(lo[0], lo[1], lo[2], lo[3]);
            s += __shfl_xor_sync(0xffffffffu, s, 1);
            s += __shfl_xor_sync(0xffffffffu, s, 2);
            if (part == 0) b2s[row] = s;
        }
    }
    if (tid * 4 < nrows)
        *(float4*)(smem + SM_YB + tid * 16) = __ldg((const float4*)(yb + b0) + tid);
    __syncthreads();

    // ---- A fragments: 4 k-chunks (hi0,hi1,lo0,lo1) x 4 regs ----
    uint32_t afr[4][4];
    {
        int arow = (lane & 7) + ((lane >> 3) & 1) * 8;
        int akof = (lane >> 4) * 16;
#pragma unroll
        for (int c = 0; c < 4; ++c)
            ldsm_x4(afr[c], sbase + SM_A + (qw + arow) * STRIDE + c * 32 + akof);
    }
    const int lg = lane >> 3;
    const int bsub = ((lg >> 1) << 3) + (lane & 7);
    const int bkh  = (lg & 1) << 4;
    const uint32_t bA = sbase + SM_B + bsub * STRIDE + bkh;
    const uint32_t bB = bA + 16 * STRIDE;

    float* db = (float*)(smem + SM_DOT + wid * (2 * DBUF));
    const float* ybs = (const float*)(smem + SM_YB);
    const float q2a = q2s[qw + (lane >> 2)];
    const float q2b = q2s[qw + (lane >> 2) + 8];
    const float* rwarp = r + (size_t)(q0 + qw) * NB + b0 + lane;

    float aK[16], aY[16];
#pragma unroll
    for (int i = 0; i < 16; ++i) { aK[i] = 0.f; aY[i] = 0.f; }

    float rv[2][16];
#pragma unroll
    for (int i = 0; i < 16; ++i) rv[0][i] = __ldcs(rwarp + (size_t)i * NB);

    // prologue: group 0 MMA+STS into buffer 0
    mma_sts(0, db, bA, bB, afr, q2a, q2b, lane);

    for (int s = 0; s < ngrp; ++s) {
        const int cur = s & 1;
        if (s + 1 < ngrp) {                    // prefetch next group's r
            const float* rg = rwarp + (s + 1) * GW;
#pragma unroll
            for (int i = 0; i < 16; ++i) rv[cur ^ 1][i] = __ldcs(rg + (size_t)i * NB);
        }
        __syncwarp();                          // STS(s) visible; epilogue(s-1) done
        if (s + 1 < ngrp)                      // next group's MMA overlaps epilogue(s)
            mma_sts(s + 1, db + (cur ^ 1) * (DSTR * 16), bA, bB, afr, q2a, q2b, lane);

        const float* dbc = db + cur * (DSTR * 16);
        const float b2v = b2s[s * GW + lane];
        const float ybv = ybs[s * GW + lane];
#pragma unroll
        for (int i = 0; i < 16; ++i) {
            float td = dbc[i * DSTR + lane];
            float d2 = fmaxf(td + b2v, 0.f);
            float d  = sqrta(d2);
            float kv = ex2a(fmaf(d, c1, rv[cur][i] * c2));
            aK[i] += kv;
            aY[i] = fmaf(kv, ybv, aY[i]);
        }
    }

    // ---- one-time transpose reduction, write partials ----
    float sk = treduce16(aK, lane);
    float sy = treduce16(aY, lane);
    if (!(lane & 1)) {
        int q = q0 + qw + (lane >> 1);
        g_pk [q * BSPL + blockIdx.y] = sk;
        g_pky[q * BSPL + blockIdx.y] = sy;
    }

    // ---- fused finalize ----
    __threadfence();
    __syncthreads();
    if (tid == 0)
        is_last = (atomicAdd(&g_cnt[blockIdx.x], 1) == BSPL - 1);
    __syncthreads();
    if (is_last) {
        if (tid < QPC) {
            int q = q0 + tid;
            float skv = 0.f, syv = 0.f;
#pragma unroll
            for (int s = 0; s < BSPL; ++s) {
                skv += __ldcg(&g_pk [q * BSPL + s]);
                syv += __ldcg(&g_pky[q * BSPL + s]);
            }
            out[q] = syv / (skv + 1e-8f);
        }
        if (tid == 0) g_cnt[blockIdx.x] = 0;   // self-reset for next replay
    }
}

extern "C" void kernel_launch(void* const* d_in, const int* in_sizes, int n_in,
                              void* d_out, int out_size) {
    const float* xb     = (const float*)d_in[0];
    const float* yb     = (const float*)d_in[1];
    const float* xq     = (const float*)d_in[2];
    const float* r      = (const float*)d_in[3];
    const float* sigma  = (const float*)d_in[4];
    const float* rscale = (const float*)d_in[5];
    const float* w      = (const float*)d_in[6];
    float* out = (float*)d_out;

    cudaFuncSetAttribute(main_kernel, cudaFuncAttributeMaxDynamicSharedMemorySize, SMEM_TOTAL);

    dim3 grid(NQ / QPC, BSPL);
    main_kernel<<<grid, TPB, SMEM_TOTAL>>>(xb, yb, xq, r, sigma, rscale, w, out);
}

// round 9
// speedup vs baseline: 1.0028x; 1.0028x over previous
#include <cuda_runtime.h>
#include <cuda_bf16.h>
#include <cstdint>

#define NQ 2048
#define NB 8192
#define DIM 32
#define TPB 512
#define QPC 256            // queries per CTA
#define BSPL 18            // background splits (grid.y)
#define GW  32             // group width in b
#define GTOT (NB / GW)     // 256 total groups
#define MAXB 480           // max background rows per CTA (15 groups)
#define STRIDE 144         // SMEM row stride bytes (odd*16 -> ldsm conflict-free)
#define DSTR 40            // dot buffer stride floats
#define LOG2E 1.4426950408889634f

// ---------------- device scratch ----------------
__device__ float g_pk [NQ * BSPL];
__device__ float g_pky[NQ * BSPL];
__device__ int   g_cnt[NQ / QPC];      // arrival counters (zero-init, self-resetting)

// ---------------- helpers ----------------
__device__ __forceinline__ uint32_t smem_u32(const void* p) {
    uint32_t a;
    asm("{ .reg .u64 t; cvta.to.shared.u64 t, %1; cvt.u32.u64 %0, t; }" : "=r"(a) : "l"(p));
    return a;
}
__device__ __forceinline__ void ldsm_x4(uint32_t* r, uint32_t addr) {
    asm volatile("ldmatrix.sync.aligned.m8n8.x4.shared.b16 {%0,%1,%2,%3}, [%4];"
                 : "=r"(r[0]), "=r"(r[1]), "=r"(r[2]), "=r"(r[3]) : "r"(addr));
}
__device__ __forceinline__ void mma_bf16(float* d, const uint32_t* a, const uint32_t* b) {
    asm volatile(
        "mma.sync.aligned.m16n8k16.row.col.f32.bf16.bf16.f32 "
        "{%0,%1,%2,%3}, {%4,%5,%6,%7}, {%8,%9}, {%0,%1,%2,%3};"
        : "+f"(d[0]), "+f"(d[1]), "+f"(d[2]), "+f"(d[3])
        : "r"(a[0]), "r"(a[1]), "r"(a[2]), "r"(a[3]), "r"(b[0]), "r"(b[1]));
}
__device__ __forceinline__ float ex2a(float x) {
    float y; asm("ex2.approx.ftz.f32 %0, %1;" : "=f"(y) : "f"(x)); return y;
}
__device__ __forceinline__ float sqrta(float x) {
    float y; asm("sqrt.approx.f32 %0, %1;" : "=f"(y) : "f"(x)); return y;
}
__device__ __forceinline__ void cp16(uint32_t sdst, const void* gsrc) {
    asm volatile("cp.async.cg.shared.global [%0], [%1], 16;" :: "r"(sdst), "l"(gsrc));
}
__device__ __forceinline__ void cp_commit() {
    asm volatile("cp.async.commit_group;" ::: "memory");
}

// transpose-reduce 16 regs over 32 lanes; lane L ends holding total for idx (L>>1)&15
__device__ __forceinline__ float treduce16(float* v, int lane) {
#pragma unroll
    for (int o = 16; o >= 2; o >>= 1) {
        bool up = (lane & o) != 0;
#pragma unroll
        for (int j = 0; j < 16; ++j) {
            if (j < (o >> 1)) {
                float send = up ? v[j] : v[j + (o >> 1)];
                float recv = __shfl_xor_sync(0xffffffffu, send, o);
                float keep = up ? v[j + (o >> 1)] : v[j];
                v[j] = keep + recv;
            }
        }
    }
    return v[0] + __shfl_xor_sync(0xffffffffu, v[0], 1);
}

// ---------------- SMEM layout ----------------
#define SM_A    0                              // 256*144 = 36864
#define SM_B    36864                          // 480*144 = 69120
#define SM_DOT  105984                         // 16 warps * 2560 = 40960
#define DOTSZ   (16 * DSTR * 4)
#define SM_RING 146944                         // 16 warps * 2 stages * 2048 = 65536
#define RINGW   4096                           // per-warp ring bytes
#define SM_B2   212480                         // 1920
#define SM_YB   214400                         // 1920
#define SM_Q2   216320                         // 1024
#define SMEM_TOTAL 217344

// convert 8 floats to hi/lo bf16 packs (4 uint32 each)
__device__ __forceinline__ void cvt8(const float* v, uint32_t* hi, uint32_t* lo) {
#pragma unroll
    for (int j = 0; j < 4; ++j) {
        float2 p = make_float2(v[2 * j], v[2 * j + 1]);
        __nv_bfloat162 h = __float22bfloat162_rn(p);
        hi[j] = *(uint32_t*)&h;
        float2 rres = make_float2(p.x - __bfloat162float(h.x),
                                  p.y - __bfloat162float(h.y));
        __nv_bfloat162 l = __float22bfloat162_rn(rres);
        lo[j] = *(uint32_t*)&l;
    }
}

// ---------------- fused kernel ----------------
__global__ void __launch_bounds__(TPB, 1)
main_kernel(const float* __restrict__ xb_g, const float* __restrict__ yb,
            const float* __restrict__ xq_g, const float* __restrict__ r,
            const float* __restrict__ sigma, const float* __restrict__ rscale,
            const float* __restrict__ w, float* __restrict__ out) {
    extern __shared__ char smem[];
    __shared__ int is_last;
    const uint32_t sbase = smem_u32(smem);
    const int tid = threadIdx.x, wid = tid >> 5, lane = tid & 31;
    const int q0 = blockIdx.x * QPC;
    const int g0 = (blockIdx.y * GTOT) / BSPL;
    const int g1 = ((blockIdx.y + 1) * GTOT) / BSPL;
    const int ngrp = g1 - g0;                  // 14 or 15
    const int b0 = g0 * GW;
    const int nrows = ngrp * GW;
    const int qw = wid * 16;
    const int part = tid & 3;

    // ---- r ring: issue groups 0,1 via cp.async BEFORE prep (hidden under prep) ----
    const uint32_t ringb = sbase + SM_RING + wid * RINGW +
                           (lane >> 1) * 128 + (lane & 1) * 64;
    const float* rring_g = r + (size_t)(q0 + qw + (lane >> 1)) * NB + b0 + (lane & 1) * 16;
#pragma unroll
    for (int s = 0; s < 2; ++s) {
#pragma unroll
        for (int k = 0; k < 4; ++k)
            cp16(ringb + s * 2048 + k * 16, rring_g + (size_t)s * GW + k * 4);
        cp_commit();
    }

    const float c1 = -LOG2E / __ldg(sigma);
    const float c2 = __ldg(rscale) * LOG2E;

    // ---- in-CTA prep: scale by w, split bf16 [hi|lo] ----
    float wreg[8];
    *(float4*)(wreg)     = __ldg((const float4*)(w + part * 8));
    *(float4*)(wreg + 4) = __ldg((const float4*)(w + part * 8 + 4));

    float* q2s = (float*)(smem + SM_Q2);
    float* b2s = (float*)(smem + SM_B2);

#pragma unroll
    for (int i = 0; i < 2; ++i) {              // A (queries): 256 rows
        int ch = tid + i * TPB, row = ch >> 2;
        float v[8];
        *(float4*)(v)     = __ldg((const float4*)(xq_g + (size_t)(q0 + row) * DIM + part * 8));
        *(float4*)(v + 4) = __ldg((const float4*)(xq_g + (size_t)(q0 + row) * DIM + part * 8 + 4));
        float s = 0.f;
#pragma unroll
        for (int j = 0; j < 8; ++j) { v[j] *= wreg[j]; s = fmaf(v[j], v[j], s); }
        uint32_t hi[4], lo[4];
        cvt8(v, hi, lo);
        char* base = smem + SM_A + row * STRIDE + part * 16;
        *(uint4*)(base)      = make_uint4(hi[0], hi[1], hi[2], hi[3]);
        *(uint4*)(base + 64) = make_uint4(lo[0], lo[1], lo[2], lo[3]);
        s += __shfl_xor_sync(0xffffffffu, s, 1);
        s += __shfl_xor_sync(0xffffffffu, s, 2);
        if (part == 0) q2s[row] = s;
    }
#pragma unroll
    for (int i = 0; i < 4; ++i) {              // B (backgrounds): nrows <= 480
        int ch = tid + i * TPB;
        if (ch < nrows * 4) {
            int row = ch >> 2;
            float v[8];
            *(float4*)(v)     = __ldg((const float4*)(xb_g + (size_t)(b0 + row) * DIM + part * 8));
            *(float4*)(v + 4) = __ldg((const float4*)(xb_g + (size_t)(b0 + row) * DIM + part * 8 + 4));
            float s = 0.f;
#pragma unroll
            for (int j = 0; j < 8; ++j) { v[j] *= wreg[j]; s = fmaf(v[j], v[j], s); }
            uint32_t hi[4], lo[4];
            cvt8(v, hi, lo);
            char* base = smem + SM_B + row * STRIDE + part * 16;
            *(uint4*)(base)      = make_uint4(hi[0], hi[1], hi[2], hi[3]);
            *(uint4*)(base + 64) = make_uint4(lo[0], lo[1], lo[2], lo[3]);
            s += __shfl_xor_sync(0xffffffffu, s, 1);
            s += __shfl_xor_sync(0xffffffffu, s, 2);
            if (part == 0) b2s[row] = s;
        }
    }
    if (tid * 4 < nrows)
        *(float4*)(smem + SM_YB + tid * 16) = __ldg((const float4*)(yb + b0) + tid);
    __syncthreads();

    // ---- A fragments: 4 k-chunks (hi0,hi1,lo0,lo1) x 4 regs ----
    uint32_t afr[4][4];
    {
        int arow = (lane & 7) + ((lane >> 3) & 1) * 8;
        int akof = (lane >> 4) * 16;
#pragma unroll
        for (int c = 0; c < 4; ++c)
            ldsm_x4(afr[c], sbase + SM_A + (qw + arow) * STRIDE + c * 32 + akof);
    }
    const int lg = lane >> 3;
    const int bsub = ((lg >> 1) << 3) + (lane & 7);
    const int bkh  = (lg & 1) << 4;
    const uint32_t bA = sbase + SM_B + bsub * STRIDE + bkh;       // b rows 0-15
    const uint32_t bB = bA + 16 * STRIDE;                          // b rows 16-31

    float* db = (float*)(smem + SM_DOT + wid * DOTSZ);
    const float* ringf = (const float*)(smem + SM_RING + wid * RINGW);
    const float* ybs = (const float*)(smem + SM_YB);
    const float q2a = q2s[qw + (lane >> 2)];
    const float q2b = q2s[qw + (lane >> 2) + 8];

    float aK[16], aY[16];
#pragma unroll
    for (int i = 0; i < 16; ++i) { aK[i] = 0.f; aY[i] = 0.f; }

    for (int s = 0; s < ngrp; ++s) {
        const int cur = s & 1;

        // ---- MMA: 32 b x 16 q; hi/lo fragment pairing (6 k-step pairs) ----
        float acc[4][4];
#pragma unroll
        for (int nt = 0; nt < 4; ++nt)
#pragma unroll
            for (int k = 0; k < 4; ++k) acc[nt][k] = 0.f;
        {
            uint32_t bf01[4][4], bf23[4][4];
#pragma unroll
            for (int c = 0; c < 4; ++c) {
                ldsm_x4(bf01[c], bA + s * (GW * STRIDE) + c * 32);
                ldsm_x4(bf23[c], bB + s * (GW * STRIDE) + c * 32);
            }
            const int pa[6] = {0, 1, 2, 3, 0, 1};
            const int pb[6] = {0, 1, 0, 1, 2, 3};
#pragma unroll
            for (int p = 0; p < 6; ++p) {
                mma_bf16(acc[0], afr[pa[p]], bf01[pb[p]] + 0);
                mma_bf16(acc[1], afr[pa[p]], bf01[pb[p]] + 2);
                mma_bf16(acc[2], afr[pa[p]], bf23[pb[p]] + 0);
                mma_bf16(acc[3], afr[pa[p]], bf23[pb[p]] + 2);
            }
        }

        // ---- STS dots with q2 - 2*dot folded in ----
        {
            int row = (lane >> 2), col = (lane & 3) * 2;
#pragma unroll
            for (int nt = 0; nt < 4; ++nt) {
                *(float2*)(db + row * DSTR + nt * 8 + col) =
                    make_float2(fmaf(-2.f, acc[nt][0], q2a), fmaf(-2.f, acc[nt][1], q2a));
                *(float2*)(db + (row + 8) * DSTR + nt * 8 + col) =
                    make_float2(fmaf(-2.f, acc[nt][2], q2b), fmaf(-2.f, acc[nt][3], q2b));
            }
        }
        // r group s resident + dots visible
        asm volatile("cp.async.wait_group 1;" ::: "memory");
        __syncwarp();

        // ---- epilogue: lane = b column; rv from SMEM ring (conflict-free) ----
        const float* rg = ringf + cur * 512;
        const float b2v = b2s[s * GW + lane];
        const float ybv = ybs[s * GW + lane];
#pragma unroll
        for (int i = 0; i < 16; ++i) {
            float td = db[i * DSTR + lane];
            float rvv = rg[i * 32 + lane];
            float d2 = fmaxf(td + b2v, 0.f);
            float d  = sqrta(d2);
            float kv = ex2a(fmaf(d, c1, rvv * c2));
            aK[i] += kv;
            aY[i] = fmaf(kv, ybv, aY[i]);
        }
        __syncwarp();    // dot + ring slot free for reuse

        // ---- issue cp.async for group s+2 into the slot just drained ----
        if (s + 2 < ngrp) {
#pragma unroll
            for (int k = 0; k < 4; ++k)
                cp16(ringb + cur * 2048 + k * 16, rring_g + (size_t)(s + 2) * GW + k * 4);
            cp_commit();
        }
    }

    // ---- one-time transpose reduction, write partials ----
    float sk = treduce16(aK, lane);
    float sy = treduce16(aY, lane);
    if (!(lane & 1)) {
        int q = q0 + qw + (lane >> 1);
        g_pk [q * BSPL + blockIdx.y] = sk;
        g_pky[q * BSPL + blockIdx.y] = sy;
    }

    // ---- fused finalize ----
    __threadfence();
    __syncthreads();
    if (tid == 0)
        is_last = (atomicAdd(&g_cnt[blockIdx.x], 1) == BSPL - 1);
    __syncthreads();
    if (is_last) {
        if (tid < QPC) {
            int q = q0 + tid;
            float skv = 0.f, syv = 0.f;
#pragma unroll
            for (int s = 0; s < BSPL; ++s) {
                skv += __ldcg(&g_pk [q * BSPL + s]);
                syv += __ldcg(&g_pky[q * BSPL + s]);
            }
            out[q] = syv / (skv + 1e-8f);
        }
        if (tid == 0) g_cnt[blockIdx.x] = 0;   // self-reset for next replay
    }
}

extern "C" void kernel_launch(void* const* d_in, const int* in_sizes, int n_in,
                              void* d_out, int out_size) {
    const float* xb     = (const float*)d_in[0];
    const float* yb     = (const float*)d_in[1];
    const float* xq     = (const float*)d_in[2];
    const float* r      = (const float*)d_in[3];
    const float* sigma  = (const float*)d_in[4];
    const float* rscale = (const float*)d_in[5];
    const float* w      = (const float*)d_in[6];
    float* out = (float*)d_out;

    cudaFuncSetAttribute(main_kernel, cudaFuncAttributeMaxDynamicSharedMemorySize, SMEM_TOTAL);

    dim3 grid(NQ / QPC, BSPL);
    main_kernel<<<grid, TPB, SMEM_TOTAL>>>(xb, yb, xq, r, sigma, rscale, w, out);
}

// round 10
// speedup vs baseline: 1.1179x; 1.1149x over previous
#include <cuda_runtime.h>
#include <cuda_bf16.h>
#include <cstdint>

#define NQ 2048
#define NB 8192
#define DIM 32
#define TPB 512
#define QPC 256            // queries per CTA
#define BSPL 16            // background splits (grid.y), even
#define BPC (NB / BSPL)    // 512 backgrounds per CTA
#define GW  32             // group width in b
#define NGRP (BPC / GW)    // 16 groups (compile-time!)
#define STRIDE 144         // SMEM row stride bytes (odd*16 -> ldsm conflict-free)
#define DSTR 40            // dot buffer stride floats
#define LOG2E 1.4426950408889634f

// ---------------- device scratch ----------------
__device__ float g_pk [NQ * BSPL];
__device__ float g_pky[NQ * BSPL];
__device__ int   g_cnt[NQ / QPC];      // arrival counters (zero-init, self-resetting)

// ---------------- helpers ----------------
__device__ __forceinline__ uint32_t smem_u32(const void* p) {
    uint32_t a;
    asm("{ .reg .u64 t; cvta.to.shared.u64 t, %1; cvt.u32.u64 %0, t; }" : "=r"(a) : "l"(p));
    return a;
}
__device__ __forceinline__ void ldsm_x4(uint32_t* r, uint32_t addr) {
    asm volatile("ldmatrix.sync.aligned.m8n8.x4.shared.b16 {%0,%1,%2,%3}, [%4];"
                 : "=r"(r[0]), "=r"(r[1]), "=r"(r[2]), "=r"(r[3]) : "r"(addr));
}
__device__ __forceinline__ void mma_bf16(float* d, const uint32_t* a, const uint32_t* b) {
    asm volatile(
        "mma.sync.aligned.m16n8k16.row.col.f32.bf16.bf16.f32 "
        "{%0,%1,%2,%3}, {%4,%5,%6,%7}, {%8,%9}, {%0,%1,%2,%3};"
        : "+f"(d[0]), "+f"(d[1]), "+f"(d[2]), "+f"(d[3])
        : "r"(a[0]), "r"(a[1]), "r"(a[2]), "r"(a[3]), "r"(b[0]), "r"(b[1]));
}
__device__ __forceinline__ float ex2a(float x) {
    float y; asm("ex2.approx.ftz.f32 %0, %1;" : "=f"(y) : "f"(x)); return y;
}
__device__ __forceinline__ float sqrta(float x) {
    float y; asm("sqrt.approx.f32 %0, %1;" : "=f"(y) : "f"(x)); return y;
}
__device__ __forceinline__ void cp16(uint32_t sdst, const void* gsrc) {
    asm volatile("cp.async.cg.shared.global [%0], [%1], 16;" :: "r"(sdst), "l"(gsrc));
}
__device__ __forceinline__ void cp_commit() {
    asm volatile("cp.async.commit_group;" ::: "memory");
}

// transpose-reduce 16 regs over 32 lanes; lane L ends holding total for idx (L>>1)&15
__device__ __forceinline__ float treduce16(float* v, int lane) {
#pragma unroll
    for (int o = 16; o >= 2; o >>= 1) {
        bool up = (lane & o) != 0;
#pragma unroll
        for (int j = 0; j < 16; ++j) {
            if (j < (o >> 1)) {
                float send = up ? v[j] : v[j + (o >> 1)];
                float recv = __shfl_xor_sync(0xffffffffu, send, o);
                float keep = up ? v[j + (o >> 1)] : v[j];
                v[j] = keep + recv;
            }
        }
    }
    return v[0] + __shfl_xor_sync(0xffffffffu, v[0], 1);
}

// ---------------- SMEM layout ----------------
#define SM_A    0                              // 256*144 = 36864
#define SM_B    36864                          // 512*144 = 73728
#define SM_DOT  110592                         // 16 warps * 2560 = 40960
#define DOTSZ   (16 * DSTR * 4)
#define SM_RING 151552                         // 16 warps * 2 stages * 2048 = 65536
#define RINGW   4096                           // per-warp ring bytes
#define SM_B2   217088                         // 2048
#define SM_YB   219136                         // 2048
#define SM_Q2   221184                         // 1024
#define SMEM_TOTAL 222208

// convert 8 floats to hi/lo bf16 packs (4 uint32 each)
__device__ __forceinline__ void cvt8(const float* v, uint32_t* hi, uint32_t* lo) {
#pragma unroll
    for (int j = 0; j < 4; ++j) {
        float2 p = make_float2(v[2 * j], v[2 * j + 1]);
        __nv_bfloat162 h = __float22bfloat162_rn(p);
        hi[j] = *(uint32_t*)&h;
        float2 rres = make_float2(p.x - __bfloat162float(h.x),
                                  p.y - __bfloat162float(h.y));
        __nv_bfloat162 l = __float22bfloat162_rn(rres);
        lo[j] = *(uint32_t*)&l;
    }
}

// ---------------- fused kernel ----------------
__global__ void __launch_bounds__(TPB, 1)
main_kernel(const float* __restrict__ xb_g, const float* __restrict__ yb,
            const float* __restrict__ xq_g, const float* __restrict__ r,
            const float* __restrict__ sigma, const float* __restrict__ rscale,
            const float* __restrict__ w, float* __restrict__ out) {
    extern __shared__ char smem[];
    __shared__ int is_last;
    const uint32_t sbase = smem_u32(smem);
    const int tid = threadIdx.x, wid = tid >> 5, lane = tid & 31;
    const int q0 = blockIdx.x * QPC;
    const int b0 = blockIdx.y * BPC;
    const int qw = wid * 16;
    const int part = tid & 3;

    // ---- r ring: issue groups 0,1 via cp.async BEFORE prep (hidden under prep) ----
    const uint32_t ringb = sbase + SM_RING + wid * RINGW +
                           (lane >> 1) * 128 + (lane & 1) * 64;
    const float* rring_g = r + (size_t)(q0 + qw + (lane >> 1)) * NB + b0 + (lane & 1) * 16;
#pragma unroll
    for (int s = 0; s < 2; ++s) {
#pragma unroll
        for (int k = 0; k < 4; ++k)
            cp16(ringb + s * 2048 + k * 16, rring_g + (size_t)s * GW + k * 4);
        cp_commit();
    }

    const float c1 = -LOG2E / __ldg(sigma);
    const float c2 = __ldg(rscale) * LOG2E;

    // ---- in-CTA prep: scale by w, split bf16 [hi|lo] ----
    float wreg[8];
    *(float4*)(wreg)     = __ldg((const float4*)(w + part * 8));
    *(float4*)(wreg + 4) = __ldg((const float4*)(w + part * 8 + 4));

    float* q2s = (float*)(smem + SM_Q2);
    float* b2s = (float*)(smem + SM_B2);

#pragma unroll
    for (int i = 0; i < 2; ++i) {              // A (queries): 256 rows
        int ch = tid + i * TPB, row = ch >> 2;
        float v[8];
        *(float4*)(v)     = __ldg((const float4*)(xq_g + (size_t)(q0 + row) * DIM + part * 8));
        *(float4*)(v + 4) = __ldg((const float4*)(xq_g + (size_t)(q0 + row) * DIM + part * 8 + 4));
        float s = 0.f;
#pragma unroll
        for (int j = 0; j < 8; ++j) { v[j] *= wreg[j]; s = fmaf(v[j], v[j], s); }
        uint32_t hi[4], lo[4];
        cvt8(v, hi, lo);
        char* base = smem + SM_A + row * STRIDE + part * 16;
        *(uint4*)(base)      = make_uint4(hi[0], hi[1], hi[2], hi[3]);
        *(uint4*)(base + 64) = make_uint4(lo[0], lo[1], lo[2], lo[3]);
        s += __shfl_xor_sync(0xffffffffu, s, 1);
        s += __shfl_xor_sync(0xffffffffu, s, 2);
        if (part == 0) q2s[row] = s;
    }
#pragma unroll
    for (int i = 0; i < 4; ++i) {              // B (backgrounds): 512 rows
        int ch = tid + i * TPB, row = ch >> 2;
        float v[8];
        *(float4*)(v)     = __ldg((const float4*)(xb_g + (size_t)(b0 + row) * DIM + part * 8));
        *(float4*)(v + 4) = __ldg((const float4*)(xb_g + (size_t)(b0 + row) * DIM + part * 8 + 4));
        float s = 0.f;
#pragma unroll
        for (int j = 0; j < 8; ++j) { v[j] *= wreg[j]; s = fmaf(v[j], v[j], s); }
        uint32_t hi[4], lo[4];
        cvt8(v, hi, lo);
        char* base = smem + SM_B + row * STRIDE + part * 16;
        *(uint4*)(base)      = make_uint4(hi[0], hi[1], hi[2], hi[3]);
        *(uint4*)(base + 64) = make_uint4(lo[0], lo[1], lo[2], lo[3]);
        s += __shfl_xor_sync(0xffffffffu, s, 1);
        s += __shfl_xor_sync(0xffffffffu, s, 2);
        if (part == 0) b2s[row] = s;
    }
    if (tid < 128)
        *(float4*)(smem + SM_YB + tid * 16) = __ldg((const float4*)(yb + b0) + tid);
    __syncthreads();

    // ---- A fragments: 4 k-chunks (hi0,hi1,lo0,lo1) x 4 regs ----
    uint32_t afr[4][4];
    {
        int arow = (lane & 7) + ((lane >> 3) & 1) * 8;
        int akof = (lane >> 4) * 16;
#pragma unroll
        for (int c = 0; c < 4; ++c)
            ldsm_x4(afr[c], sbase + SM_A + (qw + arow) * STRIDE + c * 32 + akof);
    }
    const int lg = lane >> 3;
    const int bsub = ((lg >> 1) << 3) + (lane & 7);
    const int bkh  = (lg & 1) << 4;
    const uint32_t bA = sbase + SM_B + bsub * STRIDE + bkh;       // b rows 0-15
    const uint32_t bB = bA + 16 * STRIDE;                          // b rows 16-31

    float* db = (float*)(smem + SM_DOT + wid * DOTSZ);
    const float* ringf = (const float*)(smem + SM_RING + wid * RINGW);
    const float* ybs = (const float*)(smem + SM_YB);
    const float q2a = q2s[qw + (lane >> 2)];
    const float q2b = q2s[qw + (lane >> 2) + 8];

    float aK[16], aY[16];
#pragma unroll
    for (int i = 0; i < 16; ++i) { aK[i] = 0.f; aY[i] = 0.f; }

#pragma unroll 2
    for (int s = 0; s < NGRP; ++s) {
        const int cur = s & 1;

        // ---- MMA: 32 b x 16 q; hi/lo fragment pairing (6 k-step pairs) ----
        float acc[4][4];
#pragma unroll
        for (int nt = 0; nt < 4; ++nt)
#pragma unroll
            for (int k = 0; k < 4; ++k) acc[nt][k] = 0.f;
        {
            uint32_t bf01[4][4], bf23[4][4];
#pragma unroll
            for (int c = 0; c < 4; ++c) {
                ldsm_x4(bf01[c], bA + s * (GW * STRIDE) + c * 32);
                ldsm_x4(bf23[c], bB + s * (GW * STRIDE) + c * 32);
            }
            const int pa[6] = {0, 1, 2, 3, 0, 1};
            const int pb[6] = {0, 1, 0, 1, 2, 3};
#pragma unroll
            for (int p = 0; p < 6; ++p) {
                mma_bf16(acc[0], afr[pa[p]], bf01[pb[p]] + 0);
                mma_bf16(acc[1], afr[pa[p]], bf01[pb[p]] + 2);
                mma_bf16(acc[2], afr[pa[p]], bf23[pb[p]] + 0);
                mma_bf16(acc[3], afr[pa[p]], bf23[pb[p]] + 2);
            }
        }

        // ---- STS dots with q2 - 2*dot folded in ----
        {
            int row = (lane >> 2), col = (lane & 3) * 2;
#pragma unroll
            for (int nt = 0; nt < 4; ++nt) {
                *(float2*)(db + row * DSTR + nt * 8 + col) =
                    make_float2(fmaf(-2.f, acc[nt][0], q2a), fmaf(-2.f, acc[nt][1], q2a));
                *(float2*)(db + (row + 8) * DSTR + nt * 8 + col) =
                    make_float2(fmaf(-2.f, acc[nt][2], q2b), fmaf(-2.f, acc[nt][3], q2b));
            }
        }
        // ring slot for group s resident; on the LAST group nothing may remain
        if (s == NGRP - 1)
            asm volatile("cp.async.wait_group 0;" ::: "memory");
        else
            asm volatile("cp.async.wait_group 1;" ::: "memory");
        __syncwarp();

        // ---- epilogue: lane = b column; rv from SMEM ring (conflict-free) ----
        const float* rg = ringf + cur * 512;
        const float b2v = b2s[s * GW + lane];
        const float ybv = ybs[s * GW + lane];
#pragma unroll
        for (int i = 0; i < 16; ++i) {
            float td = db[i * DSTR + lane];
            float rvv = rg[i * 32 + lane];
            float d2 = fmaxf(td + b2v, 0.f);
            float d  = sqrta(d2);
            float kv = ex2a(fmaf(d, c1, rvv * c2));
            aK[i] += kv;
            aY[i] = fmaf(kv, ybv, aY[i]);
        }
        __syncwarp();    // dot + ring slot free for reuse

        // ---- issue cp.async for group s+2 into the slot just drained ----
        if (s + 2 < NGRP) {
#pragma unroll
            for (int k = 0; k < 4; ++k)
                cp16(ringb + cur * 2048 + k * 16, rring_g + (size_t)(s + 2) * GW + k * 4);
            cp_commit();
        }
    }

    // ---- one-time transpose reduction, write partials ----
    float sk = treduce16(aK, lane);
    float sy = treduce16(aY, lane);
    if (!(lane & 1)) {
        int q = q0 + qw + (lane >> 1);
        g_pk [q * BSPL + blockIdx.y] = sk;
        g_pky[q * BSPL + blockIdx.y] = sy;
    }

    // ---- fused finalize ----
    __threadfence();
    __syncthreads();
    if (tid == 0)
        is_last = (atomicAdd(&g_cnt[blockIdx.x], 1) == BSPL - 1);
    __syncthreads();
    if (is_last) {
        if (tid < QPC) {
            int q = q0 + tid;
            float skv = 0.f, syv = 0.f;
#pragma unroll
            for (int s = 0; s < BSPL; ++s) {
                skv += __ldcg(&g_pk [q * BSPL + s]);
                syv += __ldcg(&g_pky[q * BSPL + s]);
            }
            out[q] = syv / (skv + 1e-8f);
        }
        if (tid == 0) g_cnt[blockIdx.x] = 0;   // self-reset for next replay
    }
}

extern "C" void kernel_launch(void* const* d_in, const int* in_sizes, int n_in,
                              void* d_out, int out_size) {
    const float* xb     = (const float*)d_in[0];
    const float* yb     = (const float*)d_in[1];
    const float* xq     = (const float*)d_in[2];
    const float* r      = (const float*)d_in[3];
    const float* sigma  = (const float*)d_in[4];
    const float* rscale = (const float*)d_in[5];
    const float* w      = (const float*)d_in[6];
    float* out = (float*)d_out;

    cudaFuncSetAttribute(main_kernel, cudaFuncAttributeMaxDynamicSharedMemorySize, SMEM_TOTAL);

    dim3 grid(NQ / QPC, BSPL);
    main_kernel<<<grid, TPB, SMEM_TOTAL>>>(xb, yb, xq, r, sigma, rscale, w, out);
}

// round 11
// speedup vs baseline: 1.2734x; 1.1390x over previous
#include <cuda_runtime.h>
#include <cuda_bf16.h>
#include <cstdint>

#define NQ 2048
#define NB 8192
#define DIM 32
#define TPB 512
#define QPC 256            // queries per CTA
#define BSPL 16            // background splits (grid.y)
#define BPC (NB / BSPL)    // 512 backgrounds per CTA
#define GW  32             // group width in b
#define NGRP (BPC / GW)    // 16 groups (compile-time)
#define STRIDE 144         // A/B SMEM row stride bytes (odd*16 -> ldsm conflict-free)
#define RSTR 40            // ring row stride in floats (160B -> staggered banks)
#define RSTAGE (16 * RSTR * 4)   // 2560 B per ring stage
#define RINGW (2 * RSTAGE)       // 5120 B per warp
#define LOG2E 1.4426950408889634f

// ---------------- device scratch ----------------
__device__ float g_pk [NQ * BSPL];
__device__ float g_pky[NQ * BSPL];
__device__ int   g_cnt[NQ / QPC];      // arrival counters (zero-init, self-resetting)

// ---------------- helpers ----------------
__device__ __forceinline__ uint32_t smem_u32(const void* p) {
    uint32_t a;
    asm("{ .reg .u64 t; cvta.to.shared.u64 t, %1; cvt.u32.u64 %0, t; }" : "=r"(a) : "l"(p));
    return a;
}
__device__ __forceinline__ void ldsm_x4(uint32_t* r, uint32_t addr) {
    asm volatile("ldmatrix.sync.aligned.m8n8.x4.shared.b16 {%0,%1,%2,%3}, [%4];"
                 : "=r"(r[0]), "=r"(r[1]), "=r"(r[2]), "=r"(r[3]) : "r"(addr));
}
__device__ __forceinline__ void mma_bf16(float* d, const uint32_t* a, const uint32_t* b) {
    asm volatile(
        "mma.sync.aligned.m16n8k16.row.col.f32.bf16.bf16.f32 "
        "{%0,%1,%2,%3}, {%4,%5,%6,%7}, {%8,%9}, {%0,%1,%2,%3};"
        : "+f"(d[0]), "+f"(d[1]), "+f"(d[2]), "+f"(d[3])
        : "r"(a[0]), "r"(a[1]), "r"(a[2]), "r"(a[3]), "r"(b[0]), "r"(b[1]));
}
__device__ __forceinline__ float ex2a(float x) {
    float y; asm("ex2.approx.ftz.f32 %0, %1;" : "=f"(y) : "f"(x)); return y;
}
__device__ __forceinline__ float sqrta(float x) {
    float y; asm("sqrt.approx.f32 %0, %1;" : "=f"(y) : "f"(x)); return y;
}
__device__ __forceinline__ void cp16(uint32_t sdst, const void* gsrc) {
    asm volatile("cp.async.cg.shared.global [%0], [%1], 16;" :: "r"(sdst), "l"(gsrc));
}
__device__ __forceinline__ void cp_commit() {
    asm volatile("cp.async.commit_group;" ::: "memory");
}

// ---------------- SMEM layout ----------------
#define SM_A    0                              // 256*144 = 36864
#define SM_B    36864                          // 512*144 = 73728
#define SM_RING 110592                         // 16 warps * 5120 = 81920
#define SM_B2   192512                         // 2048
#define SM_YB   194560                         // 2048
#define SM_Q2   196608                         // 1024
#define SMEM_TOTAL 197632

// convert 8 floats to hi/lo bf16 packs (4 uint32 each)
__device__ __forceinline__ void cvt8(const float* v, uint32_t* hi, uint32_t* lo) {
#pragma unroll
    for (int j = 0; j < 4; ++j) {
        float2 p = make_float2(v[2 * j], v[2 * j + 1]);
        __nv_bfloat162 h = __float22bfloat162_rn(p);
        hi[j] = *(uint32_t*)&h;
        float2 rres = make_float2(p.x - __bfloat162float(h.x),
                                  p.y - __bfloat162float(h.y));
        __nv_bfloat162 l = __float22bfloat162_rn(rres);
        lo[j] = *(uint32_t*)&l;
    }
}

// ---------------- fused kernel ----------------
__global__ void __launch_bounds__(TPB, 1)
main_kernel(const float* __restrict__ xb_g, const float* __restrict__ yb,
            const float* __restrict__ xq_g, const float* __restrict__ r,
            const float* __restrict__ sigma, const float* __restrict__ rscale,
            const float* __restrict__ w, float* __restrict__ out) {
    extern __shared__ char smem[];
    __shared__ int is_last;
    const uint32_t sbase = smem_u32(smem);
    const int tid = threadIdx.x, wid = tid >> 5, lane = tid & 31;
    const int q0 = blockIdx.x * QPC;
    const int b0 = blockIdx.y * BPC;
    const int qw = wid * 16;
    const int part = tid & 3;

    // ---- r ring setup: lane handles rows {rr, rr+4, rr+8, rr+12}, 16B col c8 ----
    const int rr = lane >> 3;              // 0..3
    const int c8 = lane & 7;               // 16B chunk within 128B row
    const uint32_t ringb = sbase + SM_RING + wid * RINGW;
    const float* rp[4];
#pragma unroll
    for (int i = 0; i < 4; ++i)
        rp[i] = r + (size_t)(q0 + qw + rr + 4 * i) * NB + b0 + c8 * 4;

    // prologue: issue groups 0,1 BEFORE prep (DRAM latency hides under prep)
#pragma unroll
    for (int st = 0; st < 2; ++st) {
#pragma unroll
        for (int i = 0; i < 4; ++i)
            cp16(ringb + st * RSTAGE + (rr + 4 * i) * (RSTR * 4) + c8 * 16,
                 rp[i] + (size_t)st * GW);
        cp_commit();
    }

    const float c1 = -LOG2E / __ldg(sigma);
    const float c2 = __ldg(rscale) * LOG2E;

    // ---- in-CTA prep: scale by w, split bf16 [hi|lo] ----
    float wreg[8];
    *(float4*)(wreg)     = __ldg((const float4*)(w + part * 8));
    *(float4*)(wreg + 4) = __ldg((const float4*)(w + part * 8 + 4));

    float* q2s = (float*)(smem + SM_Q2);
    float* b2s = (float*)(smem + SM_B2);

#pragma unroll
    for (int i = 0; i < 2; ++i) {              // A (queries): 256 rows
        int ch = tid + i * TPB, row = ch >> 2;
        float v[8];
        *(float4*)(v)     = __ldg((const float4*)(xq_g + (size_t)(q0 + row) * DIM + part * 8));
        *(float4*)(v + 4) = __ldg((const float4*)(xq_g + (size_t)(q0 + row) * DIM + part * 8 + 4));
        float s = 0.f;
#pragma unroll
        for (int j = 0; j < 8; ++j) { v[j] *= wreg[j]; s = fmaf(v[j], v[j], s); }
        uint32_t hi[4], lo[4];
        cvt8(v, hi, lo);
        char* base = smem + SM_A + row * STRIDE + part * 16;
        *(uint4*)(base)      = make_uint4(hi[0], hi[1], hi[2], hi[3]);
        *(uint4*)(base + 64) = make_uint4(lo[0], lo[1], lo[2], lo[3]);
        s += __shfl_xor_sync(0xffffffffu, s, 1);
        s += __shfl_xor_sync(0xffffffffu, s, 2);
        if (part == 0) q2s[row] = s;
    }
#pragma unroll
    for (int i = 0; i < 4; ++i) {              // B (backgrounds): 512 rows
        int ch = tid + i * TPB, row = ch >> 2;
        float v[8];
        *(float4*)(v)     = __ldg((const float4*)(xb_g + (size_t)(b0 + row) * DIM + part * 8));
        *(float4*)(v + 4) = __ldg((const float4*)(xb_g + (size_t)(b0 + row) * DIM + part * 8 + 4));
        float s = 0.f;
#pragma unroll
        for (int j = 0; j < 8; ++j) { v[j] *= wreg[j]; s = fmaf(v[j], v[j], s); }
        uint32_t hi[4], lo[4];
        cvt8(v, hi, lo);
        char* base = smem + SM_B + row * STRIDE + part * 16;
        *(uint4*)(base)      = make_uint4(hi[0], hi[1], hi[2], hi[3]);
        *(uint4*)(base + 64) = make_uint4(lo[0], lo[1], lo[2], lo[3]);
        s += __shfl_xor_sync(0xffffffffu, s, 1);
        s += __shfl_xor_sync(0xffffffffu, s, 2);
        if (part == 0) b2s[row] = s;
    }
    if (tid < 128)
        *(float4*)(smem + SM_YB + tid * 16) = __ldg((const float4*)(yb + b0) + tid);
    __syncthreads();

    // ---- A fragments: 4 k-chunks (hi0,hi1,lo0,lo1) x 4 regs ----
    uint32_t afr[4][4];
    {
        int arow = (lane & 7) + ((lane >> 3) & 1) * 8;
        int akof = (lane >> 4) * 16;
#pragma unroll
        for (int c = 0; c < 4; ++c)
            ldsm_x4(afr[c], sbase + SM_A + (qw + arow) * STRIDE + c * 32 + akof);
    }
    const int lg = lane >> 3;
    const int bsub = ((lg >> 1) << 3) + (lane & 7);
    const int bkh  = (lg & 1) << 4;
    const uint32_t bA = sbase + SM_B + bsub * STRIDE + bkh;       // b rows 0-15
    const uint32_t bB = bA + 16 * STRIDE;                          // b rows 16-31

    const float* ringf = (const float*)(smem + SM_RING + wid * RINGW);
    const float q2a = q2s[qw + (lane >> 2)];
    const float q2b = q2s[qw + (lane >> 2) + 8];
    const int colq = (lane >> 2);              // q row within warp tile
    const int colb = (lane & 3) * 2;           // base b col within 8-wide tile

    float aK[2] = {0.f, 0.f}, aY[2] = {0.f, 0.f};  // rows q, q+8

#pragma unroll 2
    for (int s = 0; s < NGRP; ++s) {
        const int st = s & 1;

        // ---- MMA: 32 b x 16 q; hi/lo fragment pairing (6 k-step pairs) ----
        float acc[4][4];
#pragma unroll
        for (int nt = 0; nt < 4; ++nt)
#pragma unroll
            for (int k = 0; k < 4; ++k) acc[nt][k] = 0.f;
        {
            uint32_t bf01[4][4], bf23[4][4];
#pragma unroll
            for (int c = 0; c < 4; ++c) {
                ldsm_x4(bf01[c], bA + s * (GW * STRIDE) + c * 32);
                ldsm_x4(bf23[c], bB + s * (GW * STRIDE) + c * 32);
            }
            const int pa[6] = {0, 1, 2, 3, 0, 1};
            const int pb[6] = {0, 1, 0, 1, 2, 3};
#pragma unroll
            for (int p = 0; p < 6; ++p) {
                mma_bf16(acc[0], afr[pa[p]], bf01[pb[p]] + 0);
                mma_bf16(acc[1], afr[pa[p]], bf01[pb[p]] + 2);
                mma_bf16(acc[2], afr[pa[p]], bf23[pb[p]] + 0);
                mma_bf16(acc[3], afr[pa[p]], bf23[pb[p]] + 2);
            }
        }

        // ring slot for group s resident (nothing may remain on last group)
        if (s == NGRP - 1)
            asm volatile("cp.async.wait_group 0;" ::: "memory");
        else
            asm volatile("cp.async.wait_group 1;" ::: "memory");
        __syncwarp();        // publish other lanes' async copies

        // ---- epilogue in MMA layout: thread owns (q,q+8) x 8 b cols ----
        const float* rg = ringf + st * (RSTR * 16);
#pragma unroll
        for (int nt = 0; nt < 4; ++nt) {
            const int bcol = nt * 8 + colb;
            float2 b2p = *(const float2*)(b2s + s * GW + bcol);
            float2 ybp = *(const float2*)((const float*)(smem + SM_YB) + s * GW + bcol);
            float2 r0  = *(const float2*)(rg + colq * RSTR + bcol);
            float2 r1  = *(const float2*)(rg + (colq + 8) * RSTR + bcol);
#pragma unroll
            for (int j = 0; j < 2; ++j) {
                float b2v = j ? b2p.y : b2p.x;
                float ybv = j ? ybp.y : ybp.x;
                // row q
                {
                    float d2 = fmaxf(fmaf(-2.f, acc[nt][j], q2a + b2v), 0.f);
                    float rv = j ? r0.y : r0.x;
                    float kv = ex2a(fmaf(sqrta(d2), c1, rv * c2));
                    aK[0] += kv;
                    aY[0] = fmaf(kv, ybv, aY[0]);
                }
                // row q+8
                {
                    float d2 = fmaxf(fmaf(-2.f, acc[nt][2 + j], q2b + b2v), 0.f);
                    float rv = j ? r1.y : r1.x;
                    float kv = ex2a(fmaf(sqrta(d2), c1, rv * c2));
                    aK[1] += kv;
                    aY[1] = fmaf(kv, ybv, aY[1]);
                }
            }
        }

        // ---- issue cp.async for group s+2 into the slot just drained ----
        if (s + 2 < NGRP) {
#pragma unroll
            for (int i = 0; i < 4; ++i)
                cp16(ringb + st * RSTAGE + (rr + 4 * i) * (RSTR * 4) + c8 * 16,
                     rp[i] + (size_t)(s + 2) * GW);
            cp_commit();
        }
    }

    // ---- quad reduction over b (lanes in same quad share q rows) ----
#pragma unroll
    for (int h = 0; h < 2; ++h) {
        aK[h] += __shfl_xor_sync(0xffffffffu, aK[h], 1);
        aK[h] += __shfl_xor_sync(0xffffffffu, aK[h], 2);
        aY[h] += __shfl_xor_sync(0xffffffffu, aY[h], 1);
        aY[h] += __shfl_xor_sync(0xffffffffu, aY[h], 2);
    }
    if ((lane & 3) == 0) {
#pragma unroll
        for (int h = 0; h < 2; ++h) {
            int q = q0 + qw + colq + h * 8;
            g_pk [q * BSPL + blockIdx.y] = aK[h];
            g_pky[q * BSPL + blockIdx.y] = aY[h];
        }
    }

    // ---- fused finalize ----
    __threadfence();
    __syncthreads();
    if (tid == 0)
        is_last = (atomicAdd(&g_cnt[blockIdx.x], 1) == BSPL - 1);
    __syncthreads();
    if (is_last) {
        if (tid < QPC) {
            int q = q0 + tid;
            float skv = 0.f, syv = 0.f;
#pragma unroll
            for (int s = 0; s < BSPL; ++s) {
                skv += __ldcg(&g_pk [q * BSPL + s]);
                syv += __ldcg(&g_pky[q * BSPL + s]);
            }
            out[q] = syv / (skv + 1e-8f);
        }
        if (tid == 0) g_cnt[blockIdx.x] = 0;   // self-reset for next replay
    }
}

extern "C" void kernel_launch(void* const* d_in, const int* in_sizes, int n_in,
                              void* d_out, int out_size) {
    const float* xb     = (const float*)d_in[0];
    const float* yb     = (const float*)d_in[1];
    const float* xq     = (const float*)d_in[2];
    const float* r      = (const float*)d_in[3];
    const float* sigma  = (const float*)d_in[4];
    const float* rscale = (const float*)d_in[5];
    const float* w      = (const float*)d_in[6];
    float* out = (float*)d_out;

    cudaFuncSetAttribute(main_kernel, cudaFuncAttributeMaxDynamicSharedMemorySize, SMEM_TOTAL);

    dim3 grid(NQ / QPC, BSPL);
    main_kernel<<<grid, TPB, SMEM_TOTAL>>>(xb, yb, xq, r, sigma, rscale, w, out);
}

// round 12
// speedup vs baseline: 1.3903x; 1.0918x over previous
#include <cuda_runtime.h>
#include <cuda_bf16.h>
#include <cstdint>

#define NQ 2048
#define NB 8192
#define DIM 32
#define TPB 512
#define QPC 256            // queries per CTA
#define BSPL 16            // background splits (grid.y)
#define BPC (NB / BSPL)    // 512 backgrounds per CTA
#define GW  32             // group width in b
#define NGRP (BPC / GW)    // 16 groups (compile-time)
#define STRIDE 144         // A/B SMEM row stride bytes (odd*16 -> ldsm conflict-free)
#define RSTR 40            // ring row stride in floats (160B -> conflict-free LDS.64)
#define RSTAGE (16 * RSTR * 4)   // 2560 B per ring stage
#define RINGW (2 * RSTAGE)       // 5120 B per warp
#define LOG2E 1.4426950408889634f

// ---------------- device scratch ----------------
__device__ float g_pk [NQ * BSPL];
__device__ float g_pky[NQ * BSPL];
__device__ int   g_cnt[NQ / QPC];      // arrival counters (zero-init, self-resetting)

// ---------------- helpers ----------------
__device__ __forceinline__ uint32_t smem_u32(const void* p) {
    uint32_t a;
    asm("{ .reg .u64 t; cvta.to.shared.u64 t, %1; cvt.u32.u64 %0, t; }" : "=r"(a) : "l"(p));
    return a;
}
__device__ __forceinline__ void ldsm_x4(uint32_t* r, uint32_t addr) {
    asm volatile("ldmatrix.sync.aligned.m8n8.x4.shared.b16 {%0,%1,%2,%3}, [%4];"
                 : "=r"(r[0]), "=r"(r[1]), "=r"(r[2]), "=r"(r[3]) : "r"(addr));
}
__device__ __forceinline__ void mma_bf16(float* d, const uint32_t* a, const uint32_t* b) {
    asm volatile(
        "mma.sync.aligned.m16n8k16.row.col.f32.bf16.bf16.f32 "
        "{%0,%1,%2,%3}, {%4,%5,%6,%7}, {%8,%9}, {%0,%1,%2,%3};"
        : "+f"(d[0]), "+f"(d[1]), "+f"(d[2]), "+f"(d[3])
        : "r"(a[0]), "r"(a[1]), "r"(a[2]), "r"(a[3]), "r"(b[0]), "r"(b[1]));
}
__device__ __forceinline__ float ex2a(float x) {
    float y; asm("ex2.approx.ftz.f32 %0, %1;" : "=f"(y) : "f"(x)); return y;
}
__device__ __forceinline__ float sqrta(float x) {
    float y; asm("sqrt.approx.f32 %0, %1;" : "=f"(y) : "f"(x)); return y;
}
__device__ __forceinline__ void cp16(uint32_t sdst, const void* gsrc) {
    asm volatile("cp.async.cg.shared.global [%0], [%1], 16;" :: "r"(sdst), "l"(gsrc));
}
__device__ __forceinline__ void cp_commit() {
    asm volatile("cp.async.commit_group;" ::: "memory");
}

// ---------------- SMEM layout ----------------
#define SM_A    0                              // 256*144 = 36864
#define SM_B    36864                          // 512*144 = 73728
#define SM_RING 110592                         // 16 warps * 5120 = 81920
#define SM_B2   192512                         // 2048
#define SM_YB   194560                         // 2048
#define SM_Q2   196608                         // 1024
#define SMEM_TOTAL 197632

// convert 8 floats to hi/lo bf16 packs (4 uint32 each)
__device__ __forceinline__ void cvt8(const float* v, uint32_t* hi, uint32_t* lo) {
#pragma unroll
    for (int j = 0; j < 4; ++j) {
        float2 p = make_float2(v[2 * j], v[2 * j + 1]);
        __nv_bfloat162 h = __float22bfloat162_rn(p);
        hi[j] = *(uint32_t*)&h;
        float2 rres = make_float2(p.x - __bfloat162float(h.x),
                                  p.y - __bfloat162float(h.y));
        __nv_bfloat162 l = __float22bfloat162_rn(rres);
        lo[j] = *(uint32_t*)&l;
    }
}

// ---------------- fused kernel ----------------
__global__ void __launch_bounds__(TPB, 1)
main_kernel(const float* __restrict__ xb_g, const float* __restrict__ yb,
            const float* __restrict__ xq_g, const float* __restrict__ r,
            const float* __restrict__ sigma, const float* __restrict__ rscale,
            const float* __restrict__ w, float* __restrict__ out) {
    extern __shared__ char smem[];
    __shared__ int is_last;
    const uint32_t sbase = smem_u32(smem);
    const int tid = threadIdx.x, wid = tid >> 5, lane = tid & 31;
    const int q0 = blockIdx.x * QPC;
    const int b0 = blockIdx.y * BPC;
    const int qw = wid * 16;
    const int part = tid & 3;
    // phase stagger: the 4 warps of each SMSP (wid%4 fixed, wid>>2 in 0..3)
    // start 0/4/8/12 groups apart so MUFU-heavy epilogues interleave with MMA
    const int goff = (wid >> 2) * 4;

    // ---- r ring setup: lane handles rows {rr, rr+4, rr+8, rr+12}, 16B col c8 ----
    const int rr = lane >> 3;              // 0..3
    const int c8 = lane & 7;               // 16B chunk within 128B row
    const uint32_t ringb = sbase + SM_RING + wid * RINGW;
    const float* rp[4];
#pragma unroll
    for (int i = 0; i < 4; ++i)
        rp[i] = r + (size_t)(q0 + qw + rr + 4 * i) * NB + b0 + c8 * 4;

    // prologue: issue iterations 0,1 (groups goff, goff+1) BEFORE prep
#pragma unroll
    for (int ss = 0; ss < 2; ++ss) {
        const int sg = (ss + goff) & (NGRP - 1);
#pragma unroll
        for (int i = 0; i < 4; ++i)
            cp16(ringb + ss * RSTAGE + (rr + 4 * i) * (RSTR * 4) + c8 * 16,
                 rp[i] + (size_t)sg * GW);
        cp_commit();
    }

    const float c1 = -LOG2E / __ldg(sigma);
    const float c2 = __ldg(rscale) * LOG2E;

    // ---- in-CTA prep: scale by w, split bf16 [hi|lo] ----
    float wreg[8];
    *(float4*)(wreg)     = __ldg((const float4*)(w + part * 8));
    *(float4*)(wreg + 4) = __ldg((const float4*)(w + part * 8 + 4));

    float* q2s = (float*)(smem + SM_Q2);
    float* b2s = (float*)(smem + SM_B2);

#pragma unroll
    for (int i = 0; i < 2; ++i) {              // A (queries): 256 rows
        int ch = tid + i * TPB, row = ch >> 2;
        float v[8];
        *(float4*)(v)     = __ldg((const float4*)(xq_g + (size_t)(q0 + row) * DIM + part * 8));
        *(float4*)(v + 4) = __ldg((const float4*)(xq_g + (size_t)(q0 + row) * DIM + part * 8 + 4));
        float s = 0.f;
#pragma unroll
        for (int j = 0; j < 8; ++j) { v[j] *= wreg[j]; s = fmaf(v[j], v[j], s); }
        uint32_t hi[4], lo[4];
        cvt8(v, hi, lo);
        char* base = smem + SM_A + row * STRIDE + part * 16;
        *(uint4*)(base)      = make_uint4(hi[0], hi[1], hi[2], hi[3]);
        *(uint4*)(base + 64) = make_uint4(lo[0], lo[1], lo[2], lo[3]);
        s += __shfl_xor_sync(0xffffffffu, s, 1);
        s += __shfl_xor_sync(0xffffffffu, s, 2);
        if (part == 0) q2s[row] = s;
    }
#pragma unroll
    for (int i = 0; i < 4; ++i) {              // B (backgrounds): 512 rows
        int ch = tid + i * TPB, row = ch >> 2;
        float v[8];
        *(float4*)(v)     = __ldg((const float4*)(xb_g + (size_t)(b0 + row) * DIM + part * 8));
        *(float4*)(v + 4) = __ldg((const float4*)(xb_g + (size_t)(b0 + row) * DIM + part * 8 + 4));
        float s = 0.f;
#pragma unroll
        for (int j = 0; j < 8; ++j) { v[j] *= wreg[j]; s = fmaf(v[j], v[j], s); }
        uint32_t hi[4], lo[4];
        cvt8(v, hi, lo);
        char* base = smem + SM_B + row * STRIDE + part * 16;
        *(uint4*)(base)      = make_uint4(hi[0], hi[1], hi[2], hi[3]);
        *(uint4*)(base + 64) = make_uint4(lo[0], lo[1], lo[2], lo[3]);
        s += __shfl_xor_sync(0xffffffffu, s, 1);
        s += __shfl_xor_sync(0xffffffffu, s, 2);
        if (part == 0) b2s[row] = s;
    }
    if (tid < 128)
        *(float4*)(smem + SM_YB + tid * 16) = __ldg((const float4*)(yb + b0) + tid);
    __syncthreads();

    // ---- A fragments: 4 k-chunks (hi0,hi1,lo0,lo1) x 4 regs ----
    uint32_t afr[4][4];
    {
        int arow = (lane & 7) + ((lane >> 3) & 1) * 8;
        int akof = (lane >> 4) * 16;
#pragma unroll
        for (int c = 0; c < 4; ++c)
            ldsm_x4(afr[c], sbase + SM_A + (qw + arow) * STRIDE + c * 32 + akof);
    }
    const int lg = lane >> 3;
    const int bsub = ((lg >> 1) << 3) + (lane & 7);
    const int bkh  = (lg & 1) << 4;
    const uint32_t bA = sbase + SM_B + bsub * STRIDE + bkh;       // b rows 0-15
    const uint32_t bB = bA + 16 * STRIDE;                          // b rows 16-31

    const float* ringf = (const float*)(smem + SM_RING + wid * RINGW);
    const float q2a = q2s[qw + (lane >> 2)];
    const float q2b = q2s[qw + (lane >> 2) + 8];
    const int colq = (lane >> 2);              // q row within warp tile
    const int colb = (lane & 3) * 2;           // base b col within 8-wide tile

    float aK[2] = {0.f, 0.f}, aY[2] = {0.f, 0.f};  // rows q, q+8

#pragma unroll 2
    for (int ss = 0; ss < NGRP; ++ss) {
        const int s  = (ss + goff) & (NGRP - 1);   // this warp's group
        const int st = ss & 1;                     // ring stage parity

        // ---- MMA: 32 b x 16 q; hi/lo fragment pairing (6 k-step pairs) ----
        float acc[4][4];
#pragma unroll
        for (int nt = 0; nt < 4; ++nt)
#pragma unroll
            for (int k = 0; k < 4; ++k) acc[nt][k] = 0.f;
        {
            uint32_t bf01[4][4], bf23[4][4];
#pragma unroll
            for (int c = 0; c < 4; ++c) {
                ldsm_x4(bf01[c], bA + s * (GW * STRIDE) + c * 32);
                ldsm_x4(bf23[c], bB + s * (GW * STRIDE) + c * 32);
            }
            const int pa[6] = {0, 1, 2, 3, 0, 1};
            const int pb[6] = {0, 1, 0, 1, 2, 3};
#pragma unroll
            for (int p = 0; p < 6; ++p) {
                mma_bf16(acc[0], afr[pa[p]], bf01[pb[p]] + 0);
                mma_bf16(acc[1], afr[pa[p]], bf01[pb[p]] + 2);
                mma_bf16(acc[2], afr[pa[p]], bf23[pb[p]] + 0);
                mma_bf16(acc[3], afr[pa[p]], bf23[pb[p]] + 2);
            }
        }

        // ring slot for iteration ss resident (drain fully on last iteration)
        if (ss == NGRP - 1)
            asm volatile("cp.async.wait_group 0;" ::: "memory");
        else
            asm volatile("cp.async.wait_group 1;" ::: "memory");
        __syncwarp();        // publish other lanes' async copies

        // ---- epilogue in MMA layout: thread owns (q,q+8) x 8 b cols ----
        const float* rg = ringf + st * (RSTR * 16);
#pragma unroll
        for (int nt = 0; nt < 4; ++nt) {
            const int bcol = nt * 8 + colb;
            float2 b2p = *(const float2*)(b2s + s * GW + bcol);
            float2 ybp = *(const float2*)((const float*)(smem + SM_YB) + s * GW + bcol);
            float2 r0  = *(const float2*)(rg + colq * RSTR + bcol);
            float2 r1  = *(const float2*)(rg + (colq + 8) * RSTR + bcol);
#pragma unroll
            for (int j = 0; j < 2; ++j) {
                float b2v = j ? b2p.y : b2p.x;
                float ybv = j ? ybp.y : ybp.x;
                {   // row q
                    float d2 = fmaxf(fmaf(-2.f, acc[nt][j], q2a + b2v), 0.f);
                    float rv = j ? r0.y : r0.x;
                    float kv = ex2a(fmaf(sqrta(d2), c1, rv * c2));
                    aK[0] += kv;
                    aY[0] = fmaf(kv, ybv, aY[0]);
                }
                {   // row q+8
                    float d2 = fmaxf(fmaf(-2.f, acc[nt][2 + j], q2b + b2v), 0.f);
                    float rv = j ? r1.y : r1.x;
                    float kv = ex2a(fmaf(sqrta(d2), c1, rv * c2));
                    aK[1] += kv;
                    aY[1] = fmaf(kv, ybv, aY[1]);
                }
            }
        }

        // ---- issue cp.async for iteration ss+2 into the slot just drained ----
        if (ss + 2 < NGRP) {
            const int sn = (ss + 2 + goff) & (NGRP - 1);
#pragma unroll
            for (int i = 0; i < 4; ++i)
                cp16(ringb + st * RSTAGE + (rr + 4 * i) * (RSTR * 4) + c8 * 16,
                     rp[i] + (size_t)sn * GW);
            cp_commit();
        }
    }

    // ---- quad reduction over b (lanes in same quad share q rows) ----
#pragma unroll
    for (int h = 0; h < 2; ++h) {
        aK[h] += __shfl_xor_sync(0xffffffffu, aK[h], 1);
        aK[h] += __shfl_xor_sync(0xffffffffu, aK[h], 2);
        aY[h] += __shfl_xor_sync(0xffffffffu, aY[h], 1);
        aY[h] += __shfl_xor_sync(0xffffffffu, aY[h], 2);
    }
    if ((lane & 3) == 0) {
#pragma unroll
        for (int h = 0; h < 2; ++h) {
            int q = q0 + qw + colq + h * 8;
            g_pk [q * BSPL + blockIdx.y] = aK[h];
            g_pky[q * BSPL + blockIdx.y] = aY[h];
        }
    }

    // ---- fused finalize ----
    __threadfence();
    __syncthreads();
    if (tid == 0)
        is_last = (atomicAdd(&g_cnt[blockIdx.x], 1) == BSPL - 1);
    __syncthreads();
    if (is_last) {
        if (tid < QPC) {
            int q = q0 + tid;
            float skv = 0.f, syv = 0.f;
#pragma unroll
            for (int s = 0; s < BSPL; ++s) {
                skv += __ldcg(&g_pk [q * BSPL + s]);
                syv += __ldcg(&g_pky[q * BSPL + s]);
            }
            out[q] = syv / (skv + 1e-8f);
        }
        if (tid == 0) g_cnt[blockIdx.x] = 0;   // self-reset for next replay
    }
}

extern "C" void kernel_launch(void* const* d_in, const int* in_sizes, int n_in,
                              void* d_out, int out_size) {
    const float* xb     = (const float*)d_in[0];
    const float* yb     = (const float*)d_in[1];
    const float* xq     = (const float*)d_in[2];
    const float* r      = (const float*)d_in[3];
    const float* sigma  = (const float*)d_in[4];
    const float* rscale = (const float*)d_in[5];
    const float* w      = (const float*)d_in[6];
    float* out = (float*)d_out;

    cudaFuncSetAttribute(main_kernel, cudaFuncAttributeMaxDynamicSharedMemorySize, SMEM_TOTAL);

    dim3 grid(NQ / QPC, BSPL);
    main_kernel<<<grid, TPB, SMEM_TOTAL>>>(xb, yb, xq, r, sigma, rscale, w, out);
}